// round 13
// baseline (speedup 1.0000x reference)
#include <cuda_runtime.h>
#include <cuda_fp16.h>
#include <cstdint>

#define NN 100000
#define NN_PAD 100096      // 782 * 128
#define NE_MAX 3400000
#define F_IN   512
#define F_HID  256
#define F_CLS  64
#define F_PROJ 128
#define HALF_ROWS 50048    // 391 tiles * 128

// ---------------- scratch (static device globals; no allocation) ----------------
__device__ __half g_XW1h[(size_t)NN_PAD * F_HID];  // x @ W1 (fp16)
__device__ __half g_h   [(size_t)NN_PAD * F_HID];  // relu(spmm+b1) (fp16)
__device__ __half g_HW2h[(size_t)NN_PAD * F_CLS];  // h @ W2 (fp16)
__device__ float  g_z   [(size_t)NN * F_CLS];      // spmm + b2 (fp32)
__device__ __half g_zh  [(size_t)NN_PAD * F_CLS];  // relu(z) (fp16)
__device__ __half g_w1t[F_HID * F_IN];    // W1^T [256,512]
__device__ __half g_w2t[F_CLS * F_HID];   // W2^T [64,256]
__device__ __half g_w3t[F_PROJ * F_CLS];  // W3^T [128,64]
__device__ int   g_counts[NN];
__device__ int   g_rowptr[NN + 1];
__device__ int   g_cursor[NN];
__device__ int2  g_edges[NE_MAX];   // (col, val-as-int) packed

// ---------------- PTX helpers (sm_103-safe; no tcgen05) ---------------------------
__device__ __forceinline__ uint32_t smem_to_u32(const void* p) {
    uint32_t a;
    asm("{ .reg .u64 t; cvta.to.shared.u64 t, %1; cvt.u32.u64 %0, t; }" : "=r"(a) : "l"(p));
    return a;
}
#define CP_ASYNC16(dst, src) \
    asm volatile("cp.async.cg.shared.global [%0], [%1], 16;" :: "r"(dst), "l"(src))
#define CP_COMMIT() asm volatile("cp.async.commit_group;" ::: "memory")
#define CP_WAIT(N)  asm volatile("cp.async.wait_group %0;" :: "n"(N) : "memory")

#define LDSM_X4(r, addr) \
    asm volatile("ldmatrix.sync.aligned.m8n8.x4.shared.b16 {%0,%1,%2,%3}, [%4];" \
        : "=r"((r)[0]), "=r"((r)[1]), "=r"((r)[2]), "=r"((r)[3]) : "r"(addr))

__device__ __forceinline__ void mma16816h(float* c, const uint32_t* a, uint32_t b0, uint32_t b1) {
    asm volatile("mma.sync.aligned.m16n8k16.row.col.f32.f16.f16.f32 "
        "{%0,%1,%2,%3}, {%4,%5,%6,%7}, {%8,%9}, {%0,%1,%2,%3};"
        : "+f"(c[0]), "+f"(c[1]), "+f"(c[2]), "+f"(c[3])
        : "r"(a[0]), "r"(a[1]), "r"(a[2]), "r"(a[3]), "r"(b0), "r"(b1));
}

// XOR swizzle for 64B-row tiles: row r, 16B-column c16 (0..3)
__device__ __forceinline__ uint32_t swz(int r, int c16) {
    return (uint32_t)(r * 64 + ((c16 ^ ((r >> 1) & 3)) << 4));
}

__device__ __forceinline__ void store2(float* p, float x, float y) {
    *reinterpret_cast<float2*>(p) = make_float2(x, y);
}
__device__ __forceinline__ void store2(__half* p, float x, float y) {
    *reinterpret_cast<__half2*>(p) = __floats2half2_rn(x, y);
}

// ---------------- edge bucketing --------------------------------------------------
__global__ void k_hist(const int* __restrict__ rows, int E) {
    int base = (blockIdx.x * blockDim.x + threadIdx.x) * 4;
    #pragma unroll
    for (int q = 0; q < 4; q++) {
        int e = base + q;
        if (e < E) atomicAdd(&g_counts[rows[e]], 1);
    }
}
__global__ void k_scan(int n) {
    __shared__ int part[1024];
    int tid = threadIdx.x;
    int per = (n + 1023) >> 10;
    int st = tid * per;
    int en = st + per; if (en > n) en = n;
    int s = 0;
    for (int i = st; i < en; i++) s += g_counts[i];
    part[tid] = s;
    __syncthreads();
    #pragma unroll
    for (int off = 1; off < 1024; off <<= 1) {
        int v = (tid >= off) ? part[tid - off] : 0;
        __syncthreads();
        part[tid] += v;
        __syncthreads();
    }
    int base = (tid == 0) ? 0 : part[tid - 1];
    for (int i = st; i < en; i++) {
        int c = g_counts[i];
        g_rowptr[i] = base;
        g_cursor[i] = base;
        base += c;
    }
    if (tid == 1023) g_rowptr[n] = part[1023];
}
__global__ void k_scatter(const int* __restrict__ rows, const int* __restrict__ cols,
                          const float* __restrict__ vals, int E) {
    int base = (blockIdx.x * blockDim.x + threadIdx.x) * 4;
    #pragma unroll
    for (int q = 0; q < 4; q++) {
        int e = base + q;
        if (e < E) {
            int r = rows[e];
            int p = atomicAdd(&g_cursor[r], 1);
            g_edges[p] = make_int2(cols[e], __float_as_int(vals[e]));
        }
    }
}

// ---------------- transpose: W[K,N] -> T[N,K] fp16 --------------------------------
__global__ void k_transpose_h(const float* __restrict__ W, __half* __restrict__ T,
                              int K, int N) {
    int i = blockIdx.x * blockDim.x + threadIdx.x;
    if (i >= K * N) return;
    int k = i / N, n = i % N;
    T[(size_t)n * K + k] = __float2half(W[i]);
}

// ---------------- GEMM1 v2: XW1h[M,256] = x[M,512] @ W1 -----------------------------
// x staged through REGISTERS (no fp32 smem buffer): thread t owns row t>>2, 32B unit
// t&3 of the 128x32 x tile. One __syncthreads per k-chunk; convert overlaps mma.
// smem/stage: A 8KB + B 16KB = 24KB; 3 stages = 72KB.
__global__ void __launch_bounds__(512, 1) gemm1_fused(
    const float* __restrict__ X, const __half* __restrict__ B,
    __half* __restrict__ C, int Mrows)
{
    constexpr int K_TOT = 512, N_TOT = 256, NC = 16;
    constexpr int SS = 24576;
    constexpr int OFF_A = 0, OFF_B = 8192;

    extern __shared__ __align__(128) char smem[];
    const uint32_t sb = smem_to_u32(smem);
    const int tid = threadIdx.x;
    const int wid = tid >> 5, lane = tid & 31;
    const int warpM = wid & 3, warpN = wid >> 2;
    const int m0 = blockIdx.x * 128;
    const int wm0 = warpM * 32, wn0 = warpN * 64;

    const int xr_row = tid >> 2, xr_c16 = tid & 3;
    const int grow = m0 + xr_row;
    const bool xr_ok = (grow < Mrows);
    const float* xbase = X + (size_t)(xr_ok ? grow : m0) * K_TOT + xr_c16 * 8;

    float4 xr[2][2];
    auto load_x = [&](int kc, int buf) {
        if (xr_ok) {
            const float4* p = reinterpret_cast<const float4*>(xbase + kc * 32);
            xr[buf][0] = p[0];
            xr[buf][1] = p[1];
        } else {
            xr[buf][0] = make_float4(0.f, 0.f, 0.f, 0.f);
            xr[buf][1] = make_float4(0.f, 0.f, 0.f, 0.f);
        }
    };
    auto convert_x = [&](int buf, int stage) {
        uint4 hv;
        __half2 h0 = __floats2half2_rn(xr[buf][0].x, xr[buf][0].y);
        __half2 h1 = __floats2half2_rn(xr[buf][0].z, xr[buf][0].w);
        __half2 h2 = __floats2half2_rn(xr[buf][1].x, xr[buf][1].y);
        __half2 h3 = __floats2half2_rn(xr[buf][1].z, xr[buf][1].w);
        hv.x = *(uint32_t*)&h0; hv.y = *(uint32_t*)&h1;
        hv.z = *(uint32_t*)&h2; hv.w = *(uint32_t*)&h3;
        *reinterpret_cast<uint4*>(smem + (size_t)stage * SS + OFF_A + swz(xr_row, xr_c16)) = hv;
    };
    auto cp_B = [&](int kc) {
        const uint32_t sd = sb + (uint32_t)(kc % 3) * SS + OFF_B;
        #pragma unroll
        for (int i = tid; i < 1024; i += 512) {
            int r = i >> 2, c16 = i & 3;
            const char* g = (const char*)(B + (size_t)r * K_TOT + kc * 32) + c16 * 16;
            CP_ASYNC16(sd + swz(r, c16), g);
        }
        CP_COMMIT();
    };

    float acc[2][8][4];
    #pragma unroll
    for (int i = 0; i < 2; i++)
        #pragma unroll
        for (int j = 0; j < 8; j++)
            #pragma unroll
            for (int q = 0; q < 4; q++) acc[i][j][q] = 0.f;

    // prologue: x0->buf0, x1->buf1, B0, B1 in flight; A(0) converted
    load_x(0, 0);
    cp_B(0);
    load_x(1, 1);
    cp_B(1);
    convert_x(0, 0);

    for (int kc = 0; kc < NC; kc++) {
        if (kc + 1 < NC) { CP_WAIT(1); } else { CP_WAIT(0); }
        __syncthreads();   // A(kc) converted + B(kc) landed, visible to all

        if (kc + 1 < NC) convert_x((kc + 1) & 1, (kc + 1) % 3);
        if (kc + 2 < NC) { load_x(kc + 2, kc & 1); cp_B(kc + 2); }

        const uint32_t sA = sb + (uint32_t)(kc % 3) * SS + OFF_A;
        const uint32_t sB = sb + (uint32_t)(kc % 3) * SS + OFF_B;

        #pragma unroll
        for (int ks = 0; ks < 2; ks++) {
            uint32_t a[2][4];
            #pragma unroll
            for (int mt = 0; mt < 2; mt++) {
                int row = wm0 + mt * 16 + (lane & 15);
                int c16 = ks * 2 + (lane >> 4);
                LDSM_X4(a[mt], sA + swz(row, c16));
            }
            #pragma unroll
            for (int g = 0; g < 4; g++) {
                uint32_t b[4];
                int row = wn0 + g * 16 + (lane & 15);
                int c16 = ks * 2 + (lane >> 4);
                LDSM_X4(b, sB + swz(row, c16));
                #pragma unroll
                for (int mt = 0; mt < 2; mt++)
                    #pragma unroll
                    for (int h = 0; h < 2; h++)
                        mma16816h(acc[mt][g * 2 + h], a[mt], b[h], b[2 + h]);
            }
        }
    }

    #pragma unroll
    for (int mt = 0; mt < 2; mt++) {
        int m = m0 + wm0 + mt * 16 + (lane >> 2);
        #pragma unroll
        for (int nt = 0; nt < 8; nt++) {
            int n = wn0 + nt * 8 + (lane & 3) * 2;
            if (m < Mrows)
                store2(C + (size_t)m * N_TOT + n, acc[mt][nt][0], acc[mt][nt][1]);
            if (m + 8 < Mrows)
                store2(C + (size_t)(m + 8) * N_TOT + n, acc[mt][nt][2], acc[mt][nt][3]);
        }
    }
}

// ---------------- fp16 GEMM via mma.sync, optional bias, tile offset ----------------
// 256 threads, 8 warps (4m x 2n), warp tile 32 x BN/2; BK=32, 3-stage cp.async.
template<int BN, int K_TOT, int N_TOT, typename TOUT>
__global__ void __launch_bounds__(256, 1) gemm_fp16(
    const __half* __restrict__ A, const __half* __restrict__ B,
    const float* __restrict__ bias,
    TOUT* __restrict__ C, int Mrows, int tile0)
{
    constexpr int NC = K_TOT / 32;
    constexpr int SS = 8192 + BN * 64;
    constexpr int NT16 = BN / 32;
    constexpr int NT8  = BN / 16;

    extern __shared__ __align__(128) char smem[];
    const uint32_t sb = smem_to_u32(smem);
    const int tid = threadIdx.x;
    const int wid = tid >> 5, lane = tid & 31;
    const int warpM = wid & 3, warpN = wid >> 2;
    const int m0 = (blockIdx.x + tile0) * 128;
    const int wm0 = warpM * 32;
    const int wn0 = warpN * (BN / 2);

    float acc[2][NT8][4];
    #pragma unroll
    for (int i = 0; i < 2; i++)
        #pragma unroll
        for (int j = 0; j < NT8; j++)
            #pragma unroll
            for (int q = 0; q < 4; q++) acc[i][j][q] = 0.f;

    auto load_chunk = [&](int kc) {
        const uint32_t sd = sb + (uint32_t)(kc % 3) * SS;
        #pragma unroll
        for (int i = tid; i < 512; i += 256) {
            int r = i >> 2, c16 = i & 3;
            uint32_t dst = sd + swz(r, c16);
            const char* g = (const char*)(A + (size_t)(m0 + r) * K_TOT) + kc * 64 + c16 * 16;
            CP_ASYNC16(dst, g);
        }
        #pragma unroll
        for (int i = tid; i < BN * 4; i += 256) {
            int r = i >> 2, c16 = i & 3;
            uint32_t dst = sd + 8192 + swz(r, c16);
            const char* g = (const char*)(B + (size_t)r * K_TOT) + kc * 64 + c16 * 16;
            CP_ASYNC16(dst, g);
        }
        CP_COMMIT();
    };

    load_chunk(0);
    if (NC > 1) load_chunk(1);

    for (int kc = 0; kc < NC; kc++) {
        if (kc + 1 < NC) { CP_WAIT(1); } else { CP_WAIT(0); }
        __syncthreads();
        if (kc + 2 < NC) load_chunk(kc + 2);

        const uint32_t sA = sb + (uint32_t)(kc % 3) * SS;
        const uint32_t sB = sA + 8192;

        #pragma unroll
        for (int ks = 0; ks < 2; ks++) {
            uint32_t a[2][4];
            #pragma unroll
            for (int mt = 0; mt < 2; mt++) {
                int row = wm0 + mt * 16 + (lane & 15);
                int c16 = ks * 2 + (lane >> 4);
                LDSM_X4(a[mt], sA + swz(row, c16));
            }
            #pragma unroll
            for (int g = 0; g < NT16; g++) {
                uint32_t b[4];
                int row = wn0 + g * 16 + (lane & 15);
                int c16 = ks * 2 + (lane >> 4);
                LDSM_X4(b, sB + swz(row, c16));
                #pragma unroll
                for (int mt = 0; mt < 2; mt++)
                    #pragma unroll
                    for (int h = 0; h < 2; h++)
                        mma16816h(acc[mt][g * 2 + h], a[mt], b[h], b[2 + h]);
            }
        }
        __syncthreads();
    }

    #pragma unroll
    for (int mt = 0; mt < 2; mt++) {
        int m = m0 + wm0 + mt * 16 + (lane >> 2);
        #pragma unroll
        for (int nt = 0; nt < NT8; nt++) {
            int n = wn0 + nt * 8 + (lane & 3) * 2;
            float bx = 0.f, by = 0.f;
            if (bias) {
                float2 bv = *reinterpret_cast<const float2*>(bias + n);
                bx = bv.x; by = bv.y;
            }
            if (m < Mrows)
                store2(C + (size_t)m * N_TOT + n, acc[mt][nt][0] + bx, acc[mt][nt][1] + by);
            if (m + 8 < Mrows)
                store2(C + (size_t)(m + 8) * N_TOT + n, acc[mt][nt][2] + bx, acc[mt][nt][3] + by);
        }
    }
}

// ---------------- SpMM over sorted CSR, fp16 gather (simple loop; ptxas pipelines) --
// spmm1: h = relu(spmm(adj, XW1h) + b1) -> fp16.  F=256: 32 threads/row. Row range.
template<int F>
__global__ void spmm1_fp16(const __half* __restrict__ src, const float* __restrict__ bias,
                           __half* __restrict__ dst, int row0, int rowend) {
    constexpr int TPR = F / 8;
    constexpr int RPB = 256 / TPR;
    const int lane = threadIdx.x % TPR;
    const int row  = row0 + blockIdx.x * RPB + threadIdx.x / TPR;
    if (row >= rowend) return;

    const int s = g_rowptr[row];
    const int e = g_rowptr[row + 1];
    float acc[8];
    #pragma unroll
    for (int q = 0; q < 8; q++) acc[q] = 0.f;

    const size_t loff = (size_t)lane * 8;
    for (int j = s; j < e; j++) {
        int2  ev = g_edges[j];
        float v  = __int_as_float(ev.y);
        uint4 r = *reinterpret_cast<const uint4*>(src + (size_t)ev.x * F + loff);
        float2 f0 = __half22float2(*reinterpret_cast<__half2*>(&r.x));
        float2 f1 = __half22float2(*reinterpret_cast<__half2*>(&r.y));
        float2 f2 = __half22float2(*reinterpret_cast<__half2*>(&r.z));
        float2 f3 = __half22float2(*reinterpret_cast<__half2*>(&r.w));
        acc[0] = fmaf(v, f0.x, acc[0]); acc[1] = fmaf(v, f0.y, acc[1]);
        acc[2] = fmaf(v, f1.x, acc[2]); acc[3] = fmaf(v, f1.y, acc[3]);
        acc[4] = fmaf(v, f2.x, acc[4]); acc[5] = fmaf(v, f2.y, acc[5]);
        acc[6] = fmaf(v, f3.x, acc[6]); acc[7] = fmaf(v, f3.y, acc[7]);
    }
    float4 b0 = *reinterpret_cast<const float4*>(bias + loff);
    float4 b1 = *reinterpret_cast<const float4*>(bias + loff + 4);
    acc[0] = fmaxf(acc[0] + b0.x, 0.f); acc[1] = fmaxf(acc[1] + b0.y, 0.f);
    acc[2] = fmaxf(acc[2] + b0.z, 0.f); acc[3] = fmaxf(acc[3] + b0.w, 0.f);
    acc[4] = fmaxf(acc[4] + b1.x, 0.f); acc[5] = fmaxf(acc[5] + b1.y, 0.f);
    acc[6] = fmaxf(acc[6] + b1.z, 0.f); acc[7] = fmaxf(acc[7] + b1.w, 0.f);

    uint4 hv;
    __half2 h0 = __floats2half2_rn(acc[0], acc[1]);
    __half2 h1 = __floats2half2_rn(acc[2], acc[3]);
    __half2 h2 = __floats2half2_rn(acc[4], acc[5]);
    __half2 h3 = __floats2half2_rn(acc[6], acc[7]);
    hv.x = *(uint32_t*)&h0; hv.y = *(uint32_t*)&h1;
    hv.z = *(uint32_t*)&h2; hv.w = *(uint32_t*)&h3;
    *reinterpret_cast<uint4*>(dst + (size_t)row * F + loff) = hv;
}

// spmm2: z = spmm(adj, HW2h) + b2 (fp32); zh = relu(z) fp16.  F=64: 8 threads/row.
template<int F>
__global__ void spmm2_k(const __half* __restrict__ src, const float* __restrict__ bias,
                        float* __restrict__ z, __half* __restrict__ zh, int nrows) {
    constexpr int TPR = F / 8;
    constexpr int RPB = 256 / TPR;
    const int lane = threadIdx.x % TPR;
    const int row  = blockIdx.x * RPB + threadIdx.x / TPR;
    if (row >= nrows) return;

    const int s = g_rowptr[row];
    const int e = g_rowptr[row + 1];
    float acc[8];
    #pragma unroll
    for (int q = 0; q < 8; q++) acc[q] = 0.f;

    const size_t loff = (size_t)lane * 8;
    for (int j = s; j < e; j++) {
        int2  ev = g_edges[j];
        float v  = __int_as_float(ev.y);
        uint4 r = *reinterpret_cast<const uint4*>(src + (size_t)ev.x * F + loff);
        float2 f0 = __half22float2(*reinterpret_cast<__half2*>(&r.x));
        float2 f1 = __half22float2(*reinterpret_cast<__half2*>(&r.y));
        float2 f2 = __half22float2(*reinterpret_cast<__half2*>(&r.z));
        float2 f3 = __half22float2(*reinterpret_cast<__half2*>(&r.w));
        acc[0] = fmaf(v, f0.x, acc[0]); acc[1] = fmaf(v, f0.y, acc[1]);
        acc[2] = fmaf(v, f1.x, acc[2]); acc[3] = fmaf(v, f1.y, acc[3]);
        acc[4] = fmaf(v, f2.x, acc[4]); acc[5] = fmaf(v, f2.y, acc[5]);
        acc[6] = fmaf(v, f3.x, acc[6]); acc[7] = fmaf(v, f3.y, acc[7]);
    }
    float4 b0 = *reinterpret_cast<const float4*>(bias + loff);
    float4 b1 = *reinterpret_cast<const float4*>(bias + loff + 4);
    acc[0] += b0.x; acc[1] += b0.y; acc[2] += b0.z; acc[3] += b0.w;
    acc[4] += b1.x; acc[5] += b1.y; acc[6] += b1.z; acc[7] += b1.w;

    size_t off = (size_t)row * F + loff;
    *reinterpret_cast<float4*>(z + off)     = make_float4(acc[0], acc[1], acc[2], acc[3]);
    *reinterpret_cast<float4*>(z + off + 4) = make_float4(acc[4], acc[5], acc[6], acc[7]);

    uint4 hv;
    __half2 h0 = __floats2half2_rn(fmaxf(acc[0], 0.f), fmaxf(acc[1], 0.f));
    __half2 h1 = __floats2half2_rn(fmaxf(acc[2], 0.f), fmaxf(acc[3], 0.f));
    __half2 h2 = __floats2half2_rn(fmaxf(acc[4], 0.f), fmaxf(acc[5], 0.f));
    __half2 h3 = __floats2half2_rn(fmaxf(acc[6], 0.f), fmaxf(acc[7], 0.f));
    hv.x = *(uint32_t*)&h0; hv.y = *(uint32_t*)&h1;
    hv.z = *(uint32_t*)&h2; hv.w = *(uint32_t*)&h3;
    *reinterpret_cast<uint4*>(zh + off) = hv;
}

// ---------------- log_softmax over 64 classes (warp per row) -----------------------
__global__ void k_logsoftmax(const float* __restrict__ z, float* __restrict__ out, int nrows) {
    int row  = blockIdx.x * 8 + threadIdx.x / 32;
    int lane = threadIdx.x & 31;
    if (row >= nrows) return;
    float2 v = *reinterpret_cast<const float2*>(z + (size_t)row * F_CLS + lane * 2);
    float m = fmaxf(v.x, v.y);
    #pragma unroll
    for (int off = 16; off; off >>= 1) m = fmaxf(m, __shfl_xor_sync(0xffffffffu, m, off));
    float s = expf(v.x - m) + expf(v.y - m);
    #pragma unroll
    for (int off = 16; off; off >>= 1) s += __shfl_xor_sync(0xffffffffu, s, off);
    float ls = m + logf(s);
    float2 o; o.x = v.x - ls; o.y = v.y - ls;
    *reinterpret_cast<float2*>(out + (size_t)row * F_CLS + lane * 2) = o;
}

// ---------------- launch ------------------------------------------------------------
static cudaStream_t s_side = nullptr;
static cudaEvent_t  s_evFork = nullptr, s_evJoin = nullptr;
static cudaEvent_t  s_evH0 = nullptr, s_evG0 = nullptr;
static cudaEvent_t  s_evZ = nullptr, s_evLS = nullptr;

extern "C" void kernel_launch(void* const* d_in, const int* in_sizes, int n_in,
                              void* d_out, int out_size) {
    const float* x    = (const float*)d_in[0];
    const float* vals = (const float*)d_in[1];
    const float* W1   = (const float*)d_in[2];
    const float* b1   = (const float*)d_in[3];
    const float* W2   = (const float*)d_in[4];
    const float* b2   = (const float*)d_in[5];
    const float* W3   = (const float*)d_in[6];
    const float* b3   = (const float*)d_in[7];
    const int*   rows = (const int*)d_in[8];
    const int*   cols = (const int*)d_in[9];

    const int E = in_sizes[8];
    const int M = in_sizes[0] / F_IN;   // 100000

    float* out1 = (float*)d_out;                      // log_softmax [M, 64]
    float* out2 = (float*)d_out + (size_t)M * F_CLS;  // projection  [M, 128]

    float* pz;
    int* pcounts;
    __half *pXW1h, *ph, *pHW2h, *pzh, *pw1t, *pw2t, *pw3t;
    cudaGetSymbolAddress((void**)&pXW1h, g_XW1h);
    cudaGetSymbolAddress((void**)&ph,    g_h);
    cudaGetSymbolAddress((void**)&pHW2h, g_HW2h);
    cudaGetSymbolAddress((void**)&pz,    g_z);
    cudaGetSymbolAddress((void**)&pzh,   g_zh);
    cudaGetSymbolAddress((void**)&pw1t,  g_w1t);
    cudaGetSymbolAddress((void**)&pw2t,  g_w2t);
    cudaGetSymbolAddress((void**)&pw3t,  g_w3t);
    cudaGetSymbolAddress((void**)&pcounts, g_counts);

    if (s_side == nullptr) {
        cudaStreamCreateWithFlags(&s_side, cudaStreamNonBlocking);
        cudaEventCreateWithFlags(&s_evFork, cudaEventDisableTiming);
        cudaEventCreateWithFlags(&s_evJoin, cudaEventDisableTiming);
        cudaEventCreateWithFlags(&s_evH0,   cudaEventDisableTiming);
        cudaEventCreateWithFlags(&s_evG0,   cudaEventDisableTiming);
        cudaEventCreateWithFlags(&s_evZ,    cudaEventDisableTiming);
        cudaEventCreateWithFlags(&s_evLS,   cudaEventDisableTiming);
    }

    constexpr int SMEM1 = 3 * 24576;               // gemm1_fused: 73728
    constexpr int SMEM2 = 3 * (8192 + 64 * 64);    // gemm2: 36864
    constexpr int SMEM3 = 3 * (8192 + 128 * 64);   // gemm3: 49152
    cudaFuncSetAttribute(gemm1_fused, cudaFuncAttributeMaxDynamicSharedMemorySize, SMEM1);
    cudaFuncSetAttribute(gemm_fp16<64, F_HID, F_CLS, __half>,
                         cudaFuncAttributeMaxDynamicSharedMemorySize, SMEM2);
    cudaFuncSetAttribute(gemm_fp16<128, F_CLS, F_PROJ, float>,
                         cudaFuncAttributeMaxDynamicSharedMemorySize, SMEM3);

    const int MT = NN_PAD / 128;         // 782 row tiles
    const int MT_H0 = HALF_ROWS / 128;   // 391

    // ---- fork: CSR build on side stream, concurrent with GEMM1 path -----------------
    cudaEventRecord(s_evFork, 0);
    cudaStreamWaitEvent(s_side, s_evFork, 0);

    cudaMemsetAsync(pcounts, 0, (size_t)M * sizeof(int), s_side);
    k_hist<<<(E + 1023) / 1024, 256, 0, s_side>>>(rows, E);
    k_scan<<<1, 1024, 0, s_side>>>(M);
    k_scatter<<<(E + 1023) / 1024, 256, 0, s_side>>>(rows, cols, vals, E);
    cudaEventRecord(s_evJoin, s_side);

    // ---- main stream: weight transposes + GEMM1 --------------------------------------
    k_transpose_h<<<(F_IN * F_HID + 255) / 256, 256>>>(W1, pw1t, F_IN, F_HID);
    k_transpose_h<<<(F_HID * F_CLS + 255) / 256, 256>>>(W2, pw2t, F_HID, F_CLS);
    k_transpose_h<<<(F_CLS * F_PROJ + 255) / 256, 256>>>(W3, pw3t, F_CLS, F_PROJ);

    gemm1_fused<<<MT, 512, SMEM1>>>(x, pw1t, pXW1h, M);

    // ---- join: SpMM1 needs both CSR and XW1 ------------------------------------------
    cudaStreamWaitEvent(0, s_evJoin, 0);

    // spmm1 half 0 (rows [0, HALF_ROWS))
    spmm1_fp16<F_HID><<<HALF_ROWS / 8, 256>>>(pXW1h, b1, ph, 0, HALF_ROWS < M ? HALF_ROWS : M);
    cudaEventRecord(s_evH0, 0);

    // side: gemm2 half 0 (tiles [0, 391)) overlaps spmm1 half 1
    cudaStreamWaitEvent(s_side, s_evH0, 0);
    gemm_fp16<64, F_HID, F_CLS, __half><<<dim3(MT_H0, 1), 256, SMEM2, s_side>>>(
        ph, pw2t, nullptr, pHW2h, M, 0);
    cudaEventRecord(s_evG0, s_side);

    // main: spmm1 half 1 (rows [HALF_ROWS, M))
    spmm1_fp16<F_HID><<<(M - HALF_ROWS + 7) / 8, 256>>>(pXW1h, b1, ph, HALF_ROWS, M);

    // main: gemm2 half 1 (tiles [391, 782))
    gemm_fp16<64, F_HID, F_CLS, __half><<<dim3(MT - MT_H0, 1), 256, SMEM2>>>(
        ph, pw2t, nullptr, pHW2h, M, MT_H0);

    // wait for gemm2 half 0 before spmm2 (needs all HW2h)
    cudaStreamWaitEvent(0, s_evG0, 0);

    spmm2_k<F_CLS><<<(M + 31) / 32, 256>>>(pHW2h, b2, pz, pzh, M);

    // ---- fork 2: log_softmax (out1) on side, concurrent with GEMM3 (out2) ------------
    cudaEventRecord(s_evZ, 0);
    cudaStreamWaitEvent(s_side, s_evZ, 0);
    k_logsoftmax<<<(M + 7) / 8, 256, 0, s_side>>>(pz, out1, M);
    cudaEventRecord(s_evLS, s_side);

    gemm_fp16<128, F_CLS, F_PROJ, float><<<dim3(MT, 1), 256, SMEM3>>>(
        pzh, pw3t, b3, out2, M, 0);

    cudaStreamWaitEvent(0, s_evLS, 0);
}

// round 14
// speedup vs baseline: 1.0414x; 1.0414x over previous
#include <cuda_runtime.h>
#include <cuda_fp16.h>
#include <cstdint>

#define NN 100000
#define NN_PAD 100096      // 782 * 128
#define NE_MAX 3400000
#define F_IN   512
#define F_HID  256
#define F_CLS  64
#define F_PROJ 128

// ---------------- scratch (static device globals; no allocation) ----------------
__device__ __half g_XW1h[(size_t)NN_PAD * F_HID];  // x @ W1 (fp16)
__device__ __half g_h   [(size_t)NN_PAD * F_HID];  // relu(spmm+b1) (fp16)
__device__ __half g_HW2h[(size_t)NN_PAD * F_CLS];  // h @ W2 (fp16)
__device__ __half g_zh  [(size_t)NN_PAD * F_CLS];  // relu(z) (fp16)
__device__ __half g_w1t[F_HID * F_IN];    // W1^T [256,512]
__device__ __half g_w2t[F_CLS * F_HID];   // W2^T [64,256]
__device__ __half g_w3t[F_PROJ * F_CLS];  // W3^T [128,64]
__device__ int   g_counts[NN];
__device__ int   g_rowptr[NN + 1];
__device__ int   g_cursor[NN];
__device__ int2  g_edges[NE_MAX];   // (col, val-as-int) packed

// ---------------- PTX helpers (sm_103-safe; no tcgen05) ---------------------------
__device__ __forceinline__ uint32_t smem_to_u32(const void* p) {
    uint32_t a;
    asm("{ .reg .u64 t; cvta.to.shared.u64 t, %1; cvt.u32.u64 %0, t; }" : "=r"(a) : "l"(p));
    return a;
}
#define CP_ASYNC16(dst, src) \
    asm volatile("cp.async.cg.shared.global [%0], [%1], 16;" :: "r"(dst), "l"(src))
#define CP_COMMIT() asm volatile("cp.async.commit_group;" ::: "memory")
#define CP_WAIT(N)  asm volatile("cp.async.wait_group %0;" :: "n"(N) : "memory")

#define LDSM_X4(r, addr) \
    asm volatile("ldmatrix.sync.aligned.m8n8.x4.shared.b16 {%0,%1,%2,%3}, [%4];" \
        : "=r"((r)[0]), "=r"((r)[1]), "=r"((r)[2]), "=r"((r)[3]) : "r"(addr))

__device__ __forceinline__ void mma16816h(float* c, const uint32_t* a, uint32_t b0, uint32_t b1) {
    asm volatile("mma.sync.aligned.m16n8k16.row.col.f32.f16.f16.f32 "
        "{%0,%1,%2,%3}, {%4,%5,%6,%7}, {%8,%9}, {%0,%1,%2,%3};"
        : "+f"(c[0]), "+f"(c[1]), "+f"(c[2]), "+f"(c[3])
        : "r"(a[0]), "r"(a[1]), "r"(a[2]), "r"(a[3]), "r"(b0), "r"(b1));
}

// XOR swizzle for 64B-row tiles: row r, 16B-column c16 (0..3)
__device__ __forceinline__ uint32_t swz(int r, int c16) {
    return (uint32_t)(r * 64 + ((c16 ^ ((r >> 1) & 3)) << 4));
}

__device__ __forceinline__ void store2(float* p, float x, float y) {
    *reinterpret_cast<float2*>(p) = make_float2(x, y);
}
__device__ __forceinline__ void store2(__half* p, float x, float y) {
    *reinterpret_cast<__half2*>(p) = __floats2half2_rn(x, y);
}

// ---------------- edge bucketing --------------------------------------------------
__global__ void k_hist(const int* __restrict__ rows, int E) {
    int base = (blockIdx.x * blockDim.x + threadIdx.x) * 4;
    #pragma unroll
    for (int q = 0; q < 4; q++) {
        int e = base + q;
        if (e < E) atomicAdd(&g_counts[rows[e]], 1);
    }
}
__global__ void k_scan(int n) {
    __shared__ int part[1024];
    int tid = threadIdx.x;
    int per = (n + 1023) >> 10;
    int st = tid * per;
    int en = st + per; if (en > n) en = n;
    int s = 0;
    for (int i = st; i < en; i++) s += g_counts[i];
    part[tid] = s;
    __syncthreads();
    #pragma unroll
    for (int off = 1; off < 1024; off <<= 1) {
        int v = (tid >= off) ? part[tid - off] : 0;
        __syncthreads();
        part[tid] += v;
        __syncthreads();
    }
    int base = (tid == 0) ? 0 : part[tid - 1];
    for (int i = st; i < en; i++) {
        int c = g_counts[i];
        g_rowptr[i] = base;
        g_cursor[i] = base;
        base += c;
    }
    if (tid == 1023) g_rowptr[n] = part[1023];
}
__global__ void k_scatter(const int* __restrict__ rows, const int* __restrict__ cols,
                          const float* __restrict__ vals, int E) {
    int base = (blockIdx.x * blockDim.x + threadIdx.x) * 4;
    #pragma unroll
    for (int q = 0; q < 4; q++) {
        int e = base + q;
        if (e < E) {
            int r = rows[e];
            int p = atomicAdd(&g_cursor[r], 1);
            g_edges[p] = make_int2(cols[e], __float_as_int(vals[e]));
        }
    }
}

// ---------------- transpose: W[K,N] -> T[N,K] fp16 --------------------------------
__global__ void k_transpose_h(const float* __restrict__ W, __half* __restrict__ T,
                              int K, int N) {
    int i = blockIdx.x * blockDim.x + threadIdx.x;
    if (i >= K * N) return;
    int k = i / N, n = i % N;
    T[(size_t)n * K + k] = __float2half(W[i]);
}

// ---------------- GEMM1 v2: XW1h[M,256] = x[M,512] @ W1 -----------------------------
// x staged through registers; one __syncthreads per k-chunk; convert overlaps mma.
// smem/stage: A 8KB + B 16KB = 24KB; 3 stages = 72KB.
__global__ void __launch_bounds__(512, 1) gemm1_fused(
    const float* __restrict__ X, const __half* __restrict__ B,
    __half* __restrict__ C, int Mrows)
{
    constexpr int K_TOT = 512, N_TOT = 256, NC = 16;
    constexpr int SS = 24576;
    constexpr int OFF_A = 0, OFF_B = 8192;

    extern __shared__ __align__(128) char smem[];
    const uint32_t sb = smem_to_u32(smem);
    const int tid = threadIdx.x;
    const int wid = tid >> 5, lane = tid & 31;
    const int warpM = wid & 3, warpN = wid >> 2;
    const int m0 = blockIdx.x * 128;
    const int wm0 = warpM * 32, wn0 = warpN * 64;

    const int xr_row = tid >> 2, xr_c16 = tid & 3;
    const int grow = m0 + xr_row;
    const bool xr_ok = (grow < Mrows);
    const float* xbase = X + (size_t)(xr_ok ? grow : m0) * K_TOT + xr_c16 * 8;

    float4 xr[2][2];
    auto load_x = [&](int kc, int buf) {
        if (xr_ok) {
            const float4* p = reinterpret_cast<const float4*>(xbase + kc * 32);
            xr[buf][0] = p[0];
            xr[buf][1] = p[1];
        } else {
            xr[buf][0] = make_float4(0.f, 0.f, 0.f, 0.f);
            xr[buf][1] = make_float4(0.f, 0.f, 0.f, 0.f);
        }
    };
    auto convert_x = [&](int buf, int stage) {
        uint4 hv;
        __half2 h0 = __floats2half2_rn(xr[buf][0].x, xr[buf][0].y);
        __half2 h1 = __floats2half2_rn(xr[buf][0].z, xr[buf][0].w);
        __half2 h2 = __floats2half2_rn(xr[buf][1].x, xr[buf][1].y);
        __half2 h3 = __floats2half2_rn(xr[buf][1].z, xr[buf][1].w);
        hv.x = *(uint32_t*)&h0; hv.y = *(uint32_t*)&h1;
        hv.z = *(uint32_t*)&h2; hv.w = *(uint32_t*)&h3;
        *reinterpret_cast<uint4*>(smem + (size_t)stage * SS + OFF_A + swz(xr_row, xr_c16)) = hv;
    };
    auto cp_B = [&](int kc) {
        const uint32_t sd = sb + (uint32_t)(kc % 3) * SS + OFF_B;
        #pragma unroll
        for (int i = tid; i < 1024; i += 512) {
            int r = i >> 2, c16 = i & 3;
            const char* g = (const char*)(B + (size_t)r * K_TOT + kc * 32) + c16 * 16;
            CP_ASYNC16(sd + swz(r, c16), g);
        }
        CP_COMMIT();
    };

    float acc[2][8][4];
    #pragma unroll
    for (int i = 0; i < 2; i++)
        #pragma unroll
        for (int j = 0; j < 8; j++)
            #pragma unroll
            for (int q = 0; q < 4; q++) acc[i][j][q] = 0.f;

    load_x(0, 0);
    cp_B(0);
    load_x(1, 1);
    cp_B(1);
    convert_x(0, 0);

    for (int kc = 0; kc < NC; kc++) {
        if (kc + 1 < NC) { CP_WAIT(1); } else { CP_WAIT(0); }
        __syncthreads();

        if (kc + 1 < NC) convert_x((kc + 1) & 1, (kc + 1) % 3);
        if (kc + 2 < NC) { load_x(kc + 2, kc & 1); cp_B(kc + 2); }

        const uint32_t sA = sb + (uint32_t)(kc % 3) * SS + OFF_A;
        const uint32_t sB = sb + (uint32_t)(kc % 3) * SS + OFF_B;

        #pragma unroll
        for (int ks = 0; ks < 2; ks++) {
            uint32_t a[2][4];
            #pragma unroll
            for (int mt = 0; mt < 2; mt++) {
                int row = wm0 + mt * 16 + (lane & 15);
                int c16 = ks * 2 + (lane >> 4);
                LDSM_X4(a[mt], sA + swz(row, c16));
            }
            #pragma unroll
            for (int g = 0; g < 4; g++) {
                uint32_t b[4];
                int row = wn0 + g * 16 + (lane & 15);
                int c16 = ks * 2 + (lane >> 4);
                LDSM_X4(b, sB + swz(row, c16));
                #pragma unroll
                for (int mt = 0; mt < 2; mt++)
                    #pragma unroll
                    for (int h = 0; h < 2; h++)
                        mma16816h(acc[mt][g * 2 + h], a[mt], b[h], b[2 + h]);
            }
        }
    }

    #pragma unroll
    for (int mt = 0; mt < 2; mt++) {
        int m = m0 + wm0 + mt * 16 + (lane >> 2);
        #pragma unroll
        for (int nt = 0; nt < 8; nt++) {
            int n = wn0 + nt * 8 + (lane & 3) * 2;
            if (m < Mrows)
                store2(C + (size_t)m * N_TOT + n, acc[mt][nt][0], acc[mt][nt][1]);
            if (m + 8 < Mrows)
                store2(C + (size_t)(m + 8) * N_TOT + n, acc[mt][nt][2], acc[mt][nt][3]);
        }
    }
}

// ---------------- fp16 GEMM via mma.sync, optional bias ----------------------------
// 256 threads, 8 warps (4m x 2n), warp tile 32 x BN/2; BK=32, 3-stage cp.async.
template<int BN, int K_TOT, int N_TOT, typename TOUT>
__global__ void __launch_bounds__(256, 1) gemm_fp16(
    const __half* __restrict__ A, const __half* __restrict__ B,
    const float* __restrict__ bias,
    TOUT* __restrict__ C, int Mrows)
{
    constexpr int NC = K_TOT / 32;
    constexpr int SS = 8192 + BN * 64;
    constexpr int NT16 = BN / 32;
    constexpr int NT8  = BN / 16;

    extern __shared__ __align__(128) char smem[];
    const uint32_t sb = smem_to_u32(smem);
    const int tid = threadIdx.x;
    const int wid = tid >> 5, lane = tid & 31;
    const int warpM = wid & 3, warpN = wid >> 2;
    const int m0 = blockIdx.x * 128;
    const int wm0 = warpM * 32;
    const int wn0 = warpN * (BN / 2);

    float acc[2][NT8][4];
    #pragma unroll
    for (int i = 0; i < 2; i++)
        #pragma unroll
        for (int j = 0; j < NT8; j++)
            #pragma unroll
            for (int q = 0; q < 4; q++) acc[i][j][q] = 0.f;

    auto load_chunk = [&](int kc) {
        const uint32_t sd = sb + (uint32_t)(kc % 3) * SS;
        #pragma unroll
        for (int i = tid; i < 512; i += 256) {
            int r = i >> 2, c16 = i & 3;
            uint32_t dst = sd + swz(r, c16);
            const char* g = (const char*)(A + (size_t)(m0 + r) * K_TOT) + kc * 64 + c16 * 16;
            CP_ASYNC16(dst, g);
        }
        #pragma unroll
        for (int i = tid; i < BN * 4; i += 256) {
            int r = i >> 2, c16 = i & 3;
            uint32_t dst = sd + 8192 + swz(r, c16);
            const char* g = (const char*)(B + (size_t)r * K_TOT) + kc * 64 + c16 * 16;
            CP_ASYNC16(dst, g);
        }
        CP_COMMIT();
    };

    load_chunk(0);
    if (NC > 1) load_chunk(1);

    for (int kc = 0; kc < NC; kc++) {
        if (kc + 1 < NC) { CP_WAIT(1); } else { CP_WAIT(0); }
        __syncthreads();
        if (kc + 2 < NC) load_chunk(kc + 2);

        const uint32_t sA = sb + (uint32_t)(kc % 3) * SS;
        const uint32_t sB = sA + 8192;

        #pragma unroll
        for (int ks = 0; ks < 2; ks++) {
            uint32_t a[2][4];
            #pragma unroll
            for (int mt = 0; mt < 2; mt++) {
                int row = wm0 + mt * 16 + (lane & 15);
                int c16 = ks * 2 + (lane >> 4);
                LDSM_X4(a[mt], sA + swz(row, c16));
            }
            #pragma unroll
            for (int g = 0; g < NT16; g++) {
                uint32_t b[4];
                int row = wn0 + g * 16 + (lane & 15);
                int c16 = ks * 2 + (lane >> 4);
                LDSM_X4(b, sB + swz(row, c16));
                #pragma unroll
                for (int mt = 0; mt < 2; mt++)
                    #pragma unroll
                    for (int h = 0; h < 2; h++)
                        mma16816h(acc[mt][g * 2 + h], a[mt], b[h], b[2 + h]);
            }
        }
        __syncthreads();
    }

    #pragma unroll
    for (int mt = 0; mt < 2; mt++) {
        int m = m0 + wm0 + mt * 16 + (lane >> 2);
        #pragma unroll
        for (int nt = 0; nt < NT8; nt++) {
            int n = wn0 + nt * 8 + (lane & 3) * 2;
            float bx = 0.f, by = 0.f;
            if (bias) {
                float2 bv = *reinterpret_cast<const float2*>(bias + n);
                bx = bv.x; by = bv.y;
            }
            if (m < Mrows)
                store2(C + (size_t)m * N_TOT + n, acc[mt][nt][0] + bx, acc[mt][nt][1] + by);
            if (m + 8 < Mrows)
                store2(C + (size_t)(m + 8) * N_TOT + n, acc[mt][nt][2] + bx, acc[mt][nt][3] + by);
        }
    }
}

// ---------------- SpMM over sorted CSR, fp16 gather (simple loop) -------------------
// spmm1: h = relu(spmm(adj, XW1h) + b1) -> fp16.  F=256: 32 threads/row.
template<int F>
__global__ void spmm1_fp16(const __half* __restrict__ src, const float* __restrict__ bias,
                           __half* __restrict__ dst, int nrows) {
    constexpr int TPR = F / 8;
    constexpr int RPB = 256 / TPR;
    const int lane = threadIdx.x % TPR;
    const int row  = blockIdx.x * RPB + threadIdx.x / TPR;
    if (row >= nrows) return;

    const int s = g_rowptr[row];
    const int e = g_rowptr[row + 1];
    float acc[8];
    #pragma unroll
    for (int q = 0; q < 8; q++) acc[q] = 0.f;

    const size_t loff = (size_t)lane * 8;
    for (int j = s; j < e; j++) {
        int2  ev = g_edges[j];
        float v  = __int_as_float(ev.y);
        uint4 r = *reinterpret_cast<const uint4*>(src + (size_t)ev.x * F + loff);
        float2 f0 = __half22float2(*reinterpret_cast<__half2*>(&r.x));
        float2 f1 = __half22float2(*reinterpret_cast<__half2*>(&r.y));
        float2 f2 = __half22float2(*reinterpret_cast<__half2*>(&r.z));
        float2 f3 = __half22float2(*reinterpret_cast<__half2*>(&r.w));
        acc[0] = fmaf(v, f0.x, acc[0]); acc[1] = fmaf(v, f0.y, acc[1]);
        acc[2] = fmaf(v, f1.x, acc[2]); acc[3] = fmaf(v, f1.y, acc[3]);
        acc[4] = fmaf(v, f2.x, acc[4]); acc[5] = fmaf(v, f2.y, acc[5]);
        acc[6] = fmaf(v, f3.x, acc[6]); acc[7] = fmaf(v, f3.y, acc[7]);
    }
    float4 b0 = *reinterpret_cast<const float4*>(bias + loff);
    float4 b1 = *reinterpret_cast<const float4*>(bias + loff + 4);
    acc[0] = fmaxf(acc[0] + b0.x, 0.f); acc[1] = fmaxf(acc[1] + b0.y, 0.f);
    acc[2] = fmaxf(acc[2] + b0.z, 0.f); acc[3] = fmaxf(acc[3] + b0.w, 0.f);
    acc[4] = fmaxf(acc[4] + b1.x, 0.f); acc[5] = fmaxf(acc[5] + b1.y, 0.f);
    acc[6] = fmaxf(acc[6] + b1.z, 0.f); acc[7] = fmaxf(acc[7] + b1.w, 0.f);

    uint4 hv;
    __half2 h0 = __floats2half2_rn(acc[0], acc[1]);
    __half2 h1 = __floats2half2_rn(acc[2], acc[3]);
    __half2 h2 = __floats2half2_rn(acc[4], acc[5]);
    __half2 h3 = __floats2half2_rn(acc[6], acc[7]);
    hv.x = *(uint32_t*)&h0; hv.y = *(uint32_t*)&h1;
    hv.z = *(uint32_t*)&h2; hv.w = *(uint32_t*)&h3;
    *reinterpret_cast<uint4*>(dst + (size_t)row * F + loff) = hv;
}

// spmm2 fused (R6-proven): z in regs; out1 = log_softmax(z); zh = relu(z) fp16.
// F=64: 8 threads/row, 32 rows/block; M % 32 == 0 in padded launch -> uniform shuffle.
template<int F>
__global__ void spmm2_fused(const __half* __restrict__ src, const float* __restrict__ bias,
                            float* __restrict__ out1, __half* __restrict__ zh, int nrows) {
    constexpr int TPR = F / 8;              // 8
    constexpr int RPB = 256 / TPR;          // 32
    const int lane = threadIdx.x % TPR;
    const int row  = blockIdx.x * RPB + threadIdx.x / TPR;
    if (row >= nrows) return;

    const int s = g_rowptr[row];
    const int e = g_rowptr[row + 1];
    float acc[8];
    #pragma unroll
    for (int q = 0; q < 8; q++) acc[q] = 0.f;

    const size_t loff = (size_t)lane * 8;
    for (int j = s; j < e; j++) {
        int2  ev = g_edges[j];
        float v  = __int_as_float(ev.y);
        uint4 r = *reinterpret_cast<const uint4*>(src + (size_t)ev.x * F + loff);
        float2 f0 = __half22float2(*reinterpret_cast<__half2*>(&r.x));
        float2 f1 = __half22float2(*reinterpret_cast<__half2*>(&r.y));
        float2 f2 = __half22float2(*reinterpret_cast<__half2*>(&r.z));
        float2 f3 = __half22float2(*reinterpret_cast<__half2*>(&r.w));
        acc[0] = fmaf(v, f0.x, acc[0]); acc[1] = fmaf(v, f0.y, acc[1]);
        acc[2] = fmaf(v, f1.x, acc[2]); acc[3] = fmaf(v, f1.y, acc[3]);
        acc[4] = fmaf(v, f2.x, acc[4]); acc[5] = fmaf(v, f2.y, acc[5]);
        acc[6] = fmaf(v, f3.x, acc[6]); acc[7] = fmaf(v, f3.y, acc[7]);
    }
    float4 b0 = *reinterpret_cast<const float4*>(bias + loff);
    float4 b1 = *reinterpret_cast<const float4*>(bias + loff + 4);
    acc[0] += b0.x; acc[1] += b0.y; acc[2] += b0.z; acc[3] += b0.w;
    acc[4] += b1.x; acc[5] += b1.y; acc[6] += b1.z; acc[7] += b1.w;

    size_t off = (size_t)row * F + loff;
    uint4 hv;
    __half2 h0 = __floats2half2_rn(fmaxf(acc[0], 0.f), fmaxf(acc[1], 0.f));
    __half2 h1 = __floats2half2_rn(fmaxf(acc[2], 0.f), fmaxf(acc[3], 0.f));
    __half2 h2 = __floats2half2_rn(fmaxf(acc[4], 0.f), fmaxf(acc[5], 0.f));
    __half2 h3 = __floats2half2_rn(fmaxf(acc[6], 0.f), fmaxf(acc[7], 0.f));
    hv.x = *(uint32_t*)&h0; hv.y = *(uint32_t*)&h1;
    hv.z = *(uint32_t*)&h2; hv.w = *(uint32_t*)&h3;
    *reinterpret_cast<uint4*>(zh + off) = hv;

    float m = acc[0];
    #pragma unroll
    for (int q = 1; q < 8; q++) m = fmaxf(m, acc[q]);
    #pragma unroll
    for (int o = 1; o < 8; o <<= 1) m = fmaxf(m, __shfl_xor_sync(0xffffffffu, m, o));
    float ssum = 0.f;
    #pragma unroll
    for (int q = 0; q < 8; q++) ssum += expf(acc[q] - m);
    #pragma unroll
    for (int o = 1; o < 8; o <<= 1) ssum += __shfl_xor_sync(0xffffffffu, ssum, o);
    float ls = m + logf(ssum);

    *reinterpret_cast<float4*>(out1 + off) =
        make_float4(acc[0] - ls, acc[1] - ls, acc[2] - ls, acc[3] - ls);
    *reinterpret_cast<float4*>(out1 + off + 4) =
        make_float4(acc[4] - ls, acc[5] - ls, acc[6] - ls, acc[7] - ls);
}

// ---------------- launch ------------------------------------------------------------
static cudaStream_t s_side = nullptr;
static cudaEvent_t  s_evFork = nullptr, s_evJoin = nullptr;

extern "C" void kernel_launch(void* const* d_in, const int* in_sizes, int n_in,
                              void* d_out, int out_size) {
    const float* x    = (const float*)d_in[0];
    const float* vals = (const float*)d_in[1];
    const float* W1   = (const float*)d_in[2];
    const float* b1   = (const float*)d_in[3];
    const float* W2   = (const float*)d_in[4];
    const float* b2   = (const float*)d_in[5];
    const float* W3   = (const float*)d_in[6];
    const float* b3   = (const float*)d_in[7];
    const int*   rows = (const int*)d_in[8];
    const int*   cols = (const int*)d_in[9];

    const int E = in_sizes[8];
    const int M = in_sizes[0] / F_IN;   // 100000

    float* out1 = (float*)d_out;                      // log_softmax [M, 64]
    float* out2 = (float*)d_out + (size_t)M * F_CLS;  // projection  [M, 128]

    int* pcounts;
    __half *pXW1h, *ph, *pHW2h, *pzh, *pw1t, *pw2t, *pw3t;
    cudaGetSymbolAddress((void**)&pXW1h, g_XW1h);
    cudaGetSymbolAddress((void**)&ph,    g_h);
    cudaGetSymbolAddress((void**)&pHW2h, g_HW2h);
    cudaGetSymbolAddress((void**)&pzh,   g_zh);
    cudaGetSymbolAddress((void**)&pw1t,  g_w1t);
    cudaGetSymbolAddress((void**)&pw2t,  g_w2t);
    cudaGetSymbolAddress((void**)&pw3t,  g_w3t);
    cudaGetSymbolAddress((void**)&pcounts, g_counts);

    if (s_side == nullptr) {
        cudaStreamCreateWithFlags(&s_side, cudaStreamNonBlocking);
        cudaEventCreateWithFlags(&s_evFork, cudaEventDisableTiming);
        cudaEventCreateWithFlags(&s_evJoin, cudaEventDisableTiming);
    }

    constexpr int SMEM1 = 3 * 24576;               // gemm1_fused: 73728
    constexpr int SMEM2 = 3 * (8192 + 64 * 64);    // gemm2: 36864
    constexpr int SMEM3 = 3 * (8192 + 128 * 64);   // gemm3: 49152
    cudaFuncSetAttribute(gemm1_fused, cudaFuncAttributeMaxDynamicSharedMemorySize, SMEM1);
    cudaFuncSetAttribute(gemm_fp16<64, F_HID, F_CLS, __half>,
                         cudaFuncAttributeMaxDynamicSharedMemorySize, SMEM2);
    cudaFuncSetAttribute(gemm_fp16<128, F_CLS, F_PROJ, float>,
                         cudaFuncAttributeMaxDynamicSharedMemorySize, SMEM3);

    const int MT = NN_PAD / 128;  // 782 row tiles

    // ---- fork: CSR build on side stream, concurrent with GEMM1 path -----------------
    cudaEventRecord(s_evFork, 0);
    cudaStreamWaitEvent(s_side, s_evFork, 0);

    cudaMemsetAsync(pcounts, 0, (size_t)M * sizeof(int), s_side);
    k_hist<<<(E + 1023) / 1024, 256, 0, s_side>>>(rows, E);
    k_scan<<<1, 1024, 0, s_side>>>(M);
    k_scatter<<<(E + 1023) / 1024, 256, 0, s_side>>>(rows, cols, vals, E);
    cudaEventRecord(s_evJoin, s_side);

    // ---- main stream: weight transposes + GEMM1 --------------------------------------
    k_transpose_h<<<(F_IN * F_HID + 255) / 256, 256>>>(W1, pw1t, F_IN, F_HID);
    k_transpose_h<<<(F_HID * F_CLS + 255) / 256, 256>>>(W2, pw2t, F_HID, F_CLS);
    k_transpose_h<<<(F_CLS * F_PROJ + 255) / 256, 256>>>(W3, pw3t, F_CLS, F_PROJ);

    gemm1_fused<<<MT, 512, SMEM1>>>(x, pw1t, pXW1h, M);

    // ---- join: SpMM1 needs both CSR and XW1 ------------------------------------------
    cudaStreamWaitEvent(0, s_evJoin, 0);

    spmm1_fp16<F_HID><<<(M + 7) / 8, 256>>>(pXW1h, b1, ph, M);

    gemm_fp16<64, F_HID, F_CLS, __half><<<dim3(MT, 1), 256, SMEM2>>>(
        ph, pw2t, nullptr, pHW2h, M);

    // spmm2 + log_softmax + relu-split, fused (out1 written here)
    spmm2_fused<F_CLS><<<(M + 31) / 32, 256>>>(pHW2h, b2, out1, pzh, M);

    // out2 = relu(z) @ W3 + b3
    gemm_fp16<128, F_CLS, F_PROJ, float><<<dim3(MT, 1), 256, SMEM3>>>(
        pzh, pw3t, b3, out2, M);
}